// round 5
// baseline (speedup 1.0000x reference)
#include <cuda_runtime.h>
#include <math.h>

#define Hh 160
#define Ww 480
#define HW 76800
#define NP 120000

// ---------------- scratch (no allocations allowed) ----------------
__device__ int    d_win[3][HW];
__device__ int2   d_list[3][HW];
__device__ int    d_cnt[3];
__device__ float4 d_G0[9][16];    // folded red_w0 -> tap weights   [k][c/4]
__device__ float4 d_G1[9][32];    // folded red_w1 -> tap weights
__device__ float4 d_Wimg[9][64];  // sb_w[0:256]  transposed to [k][c/4]
__device__ float4 d_Wpt[9][64];   // sb_w[256:512] transposed to [k][o/4]
__device__ float  d_cb[9];        // folded bias constants per tap
__device__ float  d_ti[9][HW];    // image-part tap maps (incl cb)
__device__ float  d_tv[3][9][HW]; // voxel-part tap maps per level
__device__ float  d_tm[9][HW];    // merged tap maps

// ---------------- K0: prep (blocks 0..8) + init (blocks 9..2033) -------------
__global__ void k_initprep(const float* __restrict__ rw0, const float* __restrict__ rb0,
                           const float* __restrict__ rw1, const float* __restrict__ rb1,
                           const float* __restrict__ sbw) {
    int b = blockIdx.x;
    int tid = threadIdx.x;
    if (b < 9) {
        int k = b;
        ((float*)d_Wimg)[k * 256 + tid] = sbw[tid * 9 + k];
        ((float*)d_Wpt)[k * 256 + tid]  = sbw[(256 + tid) * 9 + k];
        if (tid < 64) {
            float s = 0.f;
            for (int o = 0; o < 256; o++) s += rw0[o * 64 + tid] * sbw[(256 + o) * 9 + k];
            ((float*)d_G0)[k * 64 + tid] = s;
        }
        if (tid < 128) {
            float s = 0.f;
            for (int o = 0; o < 256; o++) s += rw1[o * 128 + tid] * sbw[(256 + o) * 9 + k];
            ((float*)d_G1)[k * 128 + tid] = s;
        }
        if (tid == 0) {
            float s = 0.f;
            for (int o = 0; o < 256; o++) s += (rb0[o] + rb1[o]) * sbw[(256 + o) * 9 + k];
            d_cb[k] = s;
        }
    } else {
        int i = (b - 9) * 256 + tid;          // 0 .. 518399
        ((float4*)d_tv)[i] = make_float4(0.f, 0.f, 0.f, 0.f);
        if (i < 3 * HW) ((int*)d_win)[i] = -1;
        if (i < 3) d_cnt[i] = 0;
    }
}

// ---------------- K1: scatter, last-write-wins == max point index ------------
__global__ void k_scatter(const int* __restrict__ g0, const int* __restrict__ g1,
                          const int* __restrict__ g2) {
    int i = blockIdx.x * blockDim.x + threadIdx.x;
    if (i >= 3 * NP) return;
    int lvl = i / NP;
    int p = i - lvl * NP;
    const int* g = (lvl == 0) ? g0 : ((lvl == 1) ? g1 : g2);
    int x = g[2 * p];
    int y = g[2 * p + 1];
    if (x >= 0 && x < Ww && y >= 0 && y < Hh)
        atomicMax(&d_win[lvl][y * Ww + x], p);
}

// ---------------- K2: hierarchical compaction (1 global atomic / block) ------
__global__ void k_compact() {
    int lvl = blockIdx.x / 300;
    int cell = (blockIdx.x % 300) * 256 + threadIdx.x;
    int p = d_win[lvl][cell];
    bool valid = p >= 0;
    unsigned m = __ballot_sync(0xffffffffu, valid);
    int lane = threadIdx.x & 31;
    int wid = threadIdx.x >> 5;
    __shared__ int wbase[8];
    __shared__ int sbase;
    if (lane == 0) wbase[wid] = __popc(m);
    __syncthreads();
    if (threadIdx.x == 0) {
        int tot = 0;
#pragma unroll
        for (int i = 0; i < 8; i++) { int c = wbase[i]; wbase[i] = tot; tot += c; }
        sbase = atomicAdd(&d_cnt[lvl], tot);
    }
    __syncthreads();
    if (valid) {
        int pos = sbase + wbase[wid] + __popc(m & ((1u << lane) - 1));
        d_list[lvl][pos] = make_int2(cell, p);
    }
}

// ---------------- K3 bodies: image part (2 pixels/thread, scalar accs) -------
__device__ __forceinline__ void img_body(const float* __restrict__ img,
                                         const float* __restrict__ seg,
                                         float4* sW, int blk) {
    int tid = threadIdx.x;
    for (int i = tid; i < 576; i += 256) sW[i] = ((const float4*)d_Wimg)[i];
    __shared__ float scb[9];
    if (tid < 9) scb[tid] = d_cb[tid];
    __syncthreads();

    int p0 = blk * 512 + tid;                 // second pixel = p0 + 256
    float s0 = seg[HW + p0];
    float s1 = seg[HW + p0 + 256];

    float accA[9], accB[9];
#pragma unroll
    for (int k = 0; k < 9; k++) { accA[k] = 0.f; accB[k] = 0.f; }

    const float* ipA = img + p0;
    const float* ipB = img + p0 + 256;
#pragma unroll 2
    for (int c4 = 0; c4 < 64; c4++) {
        size_t o0 = (size_t)(4 * c4) * HW;
        float a0 = ipA[o0], a1 = ipA[o0 + HW], a2 = ipA[o0 + 2 * HW], a3 = ipA[o0 + 3 * HW];
        float b0 = ipB[o0], b1 = ipB[o0 + HW], b2 = ipB[o0 + 2 * HW], b3 = ipB[o0 + 3 * HW];
#pragma unroll
        for (int k = 0; k < 9; k++) {
            float4 w = sW[k * 64 + c4];
            accA[k] += a0 * w.x + a1 * w.y + a2 * w.z + a3 * w.w;
            accB[k] += b0 * w.x + b1 * w.y + b2 * w.z + b3 * w.w;
        }
    }
#pragma unroll
    for (int k = 0; k < 9; k++) {
        d_ti[k][p0]       = scb[k] + s0 * accA[k];
        d_ti[k][p0 + 256] = scb[k] + s1 * accB[k];
    }
}

// ---------------- voxel part: warp = 4 slots x 8 ch-lanes, 2 points/slot -----
template <int LVL, int C4>
__device__ __forceinline__ void voxel_body(const float* __restrict__ vf,
                                           float4* sw, int blk) {
    int n = d_cnt[LVL];
    int base = blk * 64;
    if (base >= n) return;

    int tid = threadIdx.x;
    const float4* wsrc = (LVL == 0) ? (const float4*)d_G0
                        : (LVL == 1) ? (const float4*)d_G1
                                     : (const float4*)d_Wpt;
    for (int i = tid; i < 9 * C4; i += 256) sw[i] = wsrc[i];
    __syncthreads();

    int lane = tid & 31;
    int w    = tid >> 5;
    int sub  = lane >> 3;   // slot within warp (0..3)
    int cs   = lane & 7;    // channel lane (0..7)

    int idx0 = base + w * 8 + sub * 2;
    int idx1 = idx0 + 1;
    bool ok0 = idx0 < n;
    bool ok1 = idx1 < n;
    int2 e0 = ok0 ? d_list[LVL][idx0] : make_int2(0, 0);
    int2 e1 = ok1 ? d_list[LVL][idx1] : make_int2(0, 0);
    const float4* rowA = (const float4*)vf + (size_t)e0.y * C4;
    const float4* rowB = (const float4*)vf + (size_t)e1.y * C4;

    float accA[9], accB[9];
#pragma unroll
    for (int k = 0; k < 9; k++) { accA[k] = 0.f; accB[k] = 0.f; }

#pragma unroll 2
    for (int m = 0; m < C4 / 8; m++) {
        int c4 = cs + 8 * m;
        float4 va = rowA[c4];
        float4 vb = rowB[c4];
#pragma unroll
        for (int k = 0; k < 9; k++) {
            float4 wv = sw[k * C4 + c4];
            accA[k] += va.x * wv.x + va.y * wv.y + va.z * wv.z + va.w * wv.w;
            accB[k] += vb.x * wv.x + vb.y * wv.y + vb.z * wv.z + vb.w * wv.w;
        }
    }
#pragma unroll
    for (int k = 0; k < 9; k++) {
        float sA = accA[k];
        float sB = accB[k];
        sA += __shfl_xor_sync(0xffffffffu, sA, 1);
        sB += __shfl_xor_sync(0xffffffffu, sB, 1);
        sA += __shfl_xor_sync(0xffffffffu, sA, 2);
        sB += __shfl_xor_sync(0xffffffffu, sB, 2);
        sA += __shfl_xor_sync(0xffffffffu, sA, 4);
        sB += __shfl_xor_sync(0xffffffffu, sB, 4);
        if (cs == 0) {
            if (ok0) d_tv[LVL][k][e0.x] = sA;
            if (ok1) d_tv[LVL][k][e1.x] = sB;
        }
    }
}

// ---------------- K3: merged work kernel --------------------------------------
// blocks [0,1200): lvl2  [1200,2400): lvl1  [2400,3600): lvl0  [3600,3750): img
__global__ void __launch_bounds__(256, 4) k_work(const float* __restrict__ img,
                                                 const float* __restrict__ seg,
                                                 const float* __restrict__ vf0,
                                                 const float* __restrict__ vf1,
                                                 const float* __restrict__ vf2) {
    __shared__ float4 sw[9 * 64];
    int b = blockIdx.x;
    if (b < 1200)      voxel_body<2, 64>(vf2, sw, b);
    else if (b < 2400) voxel_body<1, 32>(vf1, sw, b - 1200);
    else if (b < 3600) voxel_body<0, 16>(vf0, sw, b - 2400);
    else               img_body(img, seg, sw, b - 3600);
}

// ---------------- K4: merge the 4 tap-plane sets into one ---------------------
__global__ void k_merge() {
    int i = blockIdx.x * 256 + threadIdx.x;   // float4 index over 9*HW/4 = 172800
    const float4* a = (const float4*)d_ti;
    const float4* b = (const float4*)d_tv[0];
    const float4* c = (const float4*)d_tv[1];
    const float4* d = (const float4*)d_tv[2];
    float4 va = a[i], vb = b[i], vc = c[i], vd = d[i];
    float4 r;
    r.x = va.x + vb.x + vc.x + vd.x;
    r.y = va.y + vb.y + vc.y + vd.y;
    r.z = va.z + vb.z + vc.z + vd.z;
    r.w = va.w + vb.w + vc.w + vd.w;
    ((float4*)d_tm)[i] = r;
}

// ---------------- K5: att (into smem) + gated output stream -------------------
__global__ void __launch_bounds__(256) k_attout(const float* __restrict__ img,
                                                const float* __restrict__ seg,
                                                const float* __restrict__ sbb,
                                                float* __restrict__ out) {
    __shared__ __align__(16) float satt[256];
    int tid = threadIdx.x;
    int base = blockIdx.x * 256;
    int pix = base + tid;
    {
        int y = pix / Ww;
        int x = pix - y * Ww;
        float sum = sbb[0];
#pragma unroll
        for (int ky = 0; ky < 3; ky++) {
            int yy = y + ky - 1;
            if (yy < 0 || yy >= Hh) continue;
#pragma unroll
            for (int kx = 0; kx < 3; kx++) {
                int xx = x + kx - 1;
                if (xx < 0 || xx >= Ww) continue;
                sum += d_tm[ky * 3 + kx][yy * Ww + xx];
            }
        }
        float att = 1.f / (1.f + expf(-sum));
        satt[tid] = att * seg[HW + pix];
    }
    __syncthreads();

    // stream all 256 channels for this block's 256 pixels (64 float4 per channel)
    int q = tid & 63;          // pixel-quad within block
    int c0 = tid >> 6;         // starting channel (0..3)
    float4 a = ((const float4*)satt)[q];
    const float4* im4 = (const float4*)img;
    float4* o4 = (float4*)out;
    size_t idx = (size_t)c0 * (HW / 4) + (base / 4) + q;
#pragma unroll 8
    for (int c = c0; c < 256; c += 4, idx += (size_t)4 * (HW / 4)) {
        float4 v = im4[idx];
        v.x *= a.x; v.y *= a.y; v.z *= a.z; v.w *= a.w;
        o4[idx] = v;
    }
}

extern "C" void kernel_launch(void* const* d_in, const int* in_sizes, int n_in,
                              void* d_out, int out_size) {
    const float* img = (const float*)d_in[0];
    const float* seg = (const float*)d_in[1];

    int iv0, iv1, iv2, ig0, ig1, ig2;
    if (in_sizes[3] == 2 * NP) { iv0 = 2; ig0 = 3; iv1 = 4; ig1 = 5; iv2 = 6; ig2 = 7; }
    else                       { iv0 = 2; iv1 = 3; iv2 = 4; ig0 = 5; ig1 = 6; ig2 = 7; }

    const float* vf0 = (const float*)d_in[iv0];
    const float* vf1 = (const float*)d_in[iv1];
    const float* vf2 = (const float*)d_in[iv2];
    const int*   g0  = (const int*)d_in[ig0];
    const int*   g1  = (const int*)d_in[ig1];
    const int*   g2  = (const int*)d_in[ig2];
    const float* rw0 = (const float*)d_in[8];
    const float* rb0 = (const float*)d_in[9];
    const float* rw1 = (const float*)d_in[10];
    const float* rb1 = (const float*)d_in[11];
    const float* sbw = (const float*)d_in[12];
    const float* sbb = (const float*)d_in[13];

    k_initprep<<<2034, 256>>>(rw0, rb0, rw1, rb1, sbw);
    k_scatter<<<(3 * NP + 255) / 256, 256>>>(g0, g1, g2);
    k_compact<<<900, 256>>>();
    k_work<<<3750, 256>>>(img, seg, vf0, vf1, vf2);
    k_merge<<<675, 256>>>();
    k_attout<<<HW / 256, 256>>>(img, seg, sbb, (float*)d_out);
}

// round 7
// speedup vs baseline: 1.0728x; 1.0728x over previous
#include <cuda_runtime.h>
#include <math.h>

#define Hh 160
#define Ww 480
#define HW 76800
#define NP 120000

// ---------------- scratch (no allocations allowed) ----------------
__device__ __align__(16) int    d_win[3][HW];
__device__ __align__(16) int2   d_list[3][HW];
__device__ int    d_cnt[3];
__device__ __align__(16) float4 d_G0[9][16];    // folded red_w0 -> tap weights [k][c/4]
__device__ __align__(16) float4 d_G1[9][32];    // folded red_w1 -> tap weights
__device__ __align__(16) float4 d_Wpt[9][64];   // sb_w[256:512] transposed to [k][o/4]
__device__ __align__(16) float4 d_Wb[768];      // img tap weights, [c][12] padded rows
__device__ float  d_cb[9];                      // folded bias constants per tap
__device__ __align__(16) float  d_ti[9][HW];    // image-part tap maps
__device__ __align__(16) float  d_tv[3][9][HW]; // voxel-part tap maps per level
__device__ __align__(16) float  d_att[HW];

// ---------------- K0: prep (blocks 0..8) + init (blocks 9..2033) -------------
__global__ void k_initprep(const float* __restrict__ rw0, const float* __restrict__ rb0,
                           const float* __restrict__ rw1, const float* __restrict__ rb1,
                           const float* __restrict__ sbw) {
    int b = blockIdx.x;
    int tid = threadIdx.x;
    if (b < 9) {
        int k = b;
        ((float*)d_Wb)[tid * 12 + k] = sbw[tid * 9 + k];           // img weights, padded rows
        ((float*)d_Wpt)[k * 256 + tid] = sbw[(256 + tid) * 9 + k];
        if (tid < 64) {
            float s = 0.f;
            for (int o = 0; o < 256; o++) s += rw0[o * 64 + tid] * sbw[(256 + o) * 9 + k];
            ((float*)d_G0)[k * 64 + tid] = s;
        }
        if (tid < 128) {
            float s = 0.f;
            for (int o = 0; o < 256; o++) s += rw1[o * 128 + tid] * sbw[(256 + o) * 9 + k];
            ((float*)d_G1)[k * 128 + tid] = s;
        }
        if (tid == 0) {
            float s = 0.f;
            for (int o = 0; o < 256; o++) s += (rb0[o] + rb1[o]) * sbw[(256 + o) * 9 + k];
            d_cb[k] = s;
        }
    } else {
        int i = (b - 9) * 256 + tid;          // 0 .. 518399
        ((float4*)d_tv)[i] = make_float4(0.f, 0.f, 0.f, 0.f);
        if (i < 3 * HW) ((int*)d_win)[i] = -1;
        if (i < 3) d_cnt[i] = 0;
    }
}

// ---------------- K1: scatter, last-write-wins == max point index ------------
__global__ void k_scatter(const int* __restrict__ g0, const int* __restrict__ g1,
                          const int* __restrict__ g2) {
    int i = blockIdx.x * blockDim.x + threadIdx.x;
    if (i >= 3 * NP) return;
    int lvl = i / NP;
    int p = i - lvl * NP;
    const int* g = (lvl == 0) ? g0 : ((lvl == 1) ? g1 : g2);
    int x = g[2 * p];
    int y = g[2 * p + 1];
    if (x >= 0 && x < Ww && y >= 0 && y < Hh)
        atomicMax(&d_win[lvl][y * Ww + x], p);
}

// ---------------- K2: hierarchical compaction (1 global atomic / block) ------
__global__ void k_compact() {
    int lvl = blockIdx.x / 300;
    int cell = (blockIdx.x % 300) * 256 + threadIdx.x;
    int p = d_win[lvl][cell];
    bool valid = p >= 0;
    unsigned m = __ballot_sync(0xffffffffu, valid);
    int lane = threadIdx.x & 31;
    int wid = threadIdx.x >> 5;
    __shared__ int wbase[8];
    __shared__ int sbase;
    if (lane == 0) wbase[wid] = __popc(m);
    __syncthreads();
    if (threadIdx.x == 0) {
        int tot = 0;
#pragma unroll
        for (int i = 0; i < 8; i++) { int c = wbase[i]; wbase[i] = tot; tot += c; }
        sbase = atomicAdd(&d_cnt[lvl], tot);
    }
    __syncthreads();
    if (valid) {
        int pos = sbase + wbase[wid] + __popc(m & ((1u << lane) - 1));
        d_list[lvl][pos] = make_int2(cell, p);
    }
}

// ---------------- img part: quad-major float4 loads --------------------------
// warp = 8 quad-slots x 4 channel-lanes; lane loads float4 (4 px) per channel
__device__ __forceinline__ void img_body(const float* __restrict__ img,
                                         const float* __restrict__ seg,
                                         float* sWf, int blk) {
    int tid = threadIdx.x;
    for (int i = tid; i < 768; i += 256) ((float4*)sWf)[i] = d_Wb[i];
    __shared__ float scb[9];
    if (tid < 9) scb[tid] = d_cb[tid];
    __syncthreads();

    int lane = tid & 31;
    int w    = tid >> 5;
    int cs   = lane & 3;    // channel lane (0..3)
    int sub  = lane >> 2;   // quad slot (0..7)
    int px   = blk * 256 + w * 32 + sub * 4;

    float4 acc[9];
#pragma unroll
    for (int k = 0; k < 9; k++) acc[k] = make_float4(0.f, 0.f, 0.f, 0.f);

    for (int m = 0; m < 64; m++) {
        int c = cs + 4 * m;
        float4 v = *(const float4*)(img + (size_t)c * HW + px);
        const float* wp = sWf + c * 12;
        float4 w0 = *(const float4*)wp;
        float4 w1 = *(const float4*)(wp + 4);
        float  w8 = wp[8];
        acc[0].x += v.x * w0.x; acc[0].y += v.y * w0.x; acc[0].z += v.z * w0.x; acc[0].w += v.w * w0.x;
        acc[1].x += v.x * w0.y; acc[1].y += v.y * w0.y; acc[1].z += v.z * w0.y; acc[1].w += v.w * w0.y;
        acc[2].x += v.x * w0.z; acc[2].y += v.y * w0.z; acc[2].z += v.z * w0.z; acc[2].w += v.w * w0.z;
        acc[3].x += v.x * w0.w; acc[3].y += v.y * w0.w; acc[3].z += v.z * w0.w; acc[3].w += v.w * w0.w;
        acc[4].x += v.x * w1.x; acc[4].y += v.y * w1.x; acc[4].z += v.z * w1.x; acc[4].w += v.w * w1.x;
        acc[5].x += v.x * w1.y; acc[5].y += v.y * w1.y; acc[5].z += v.z * w1.y; acc[5].w += v.w * w1.y;
        acc[6].x += v.x * w1.z; acc[6].y += v.y * w1.z; acc[6].z += v.z * w1.z; acc[6].w += v.w * w1.z;
        acc[7].x += v.x * w1.w; acc[7].y += v.y * w1.w; acc[7].z += v.z * w1.w; acc[7].w += v.w * w1.w;
        acc[8].x += v.x * w8;   acc[8].y += v.y * w8;   acc[8].z += v.z * w8;   acc[8].w += v.w * w8;
    }

    // reduce across the 4 channel-lanes (xor 1, 2)
#pragma unroll
    for (int k = 0; k < 9; k++) {
        acc[k].x += __shfl_xor_sync(0xffffffffu, acc[k].x, 1);
        acc[k].y += __shfl_xor_sync(0xffffffffu, acc[k].y, 1);
        acc[k].z += __shfl_xor_sync(0xffffffffu, acc[k].z, 1);
        acc[k].w += __shfl_xor_sync(0xffffffffu, acc[k].w, 1);
        acc[k].x += __shfl_xor_sync(0xffffffffu, acc[k].x, 2);
        acc[k].y += __shfl_xor_sync(0xffffffffu, acc[k].y, 2);
        acc[k].z += __shfl_xor_sync(0xffffffffu, acc[k].z, 2);
        acc[k].w += __shfl_xor_sync(0xffffffffu, acc[k].w, 2);
    }
    if (cs == 0) {
        float4 sg = *(const float4*)(seg + HW + px);
#pragma unroll
        for (int k = 0; k < 9; k++) {
            float4 o;
            o.x = scb[k] + sg.x * acc[k].x;
            o.y = scb[k] + sg.y * acc[k].y;
            o.z = scb[k] + sg.z * acc[k].z;
            o.w = scb[k] + sg.w * acc[k].w;
            *(float4*)(&d_ti[k][px]) = o;
        }
    }
}

// ---------------- voxel part: warp = 4 slots x 8 ch-lanes, 2 points/slot -----
template <int LVL, int C4>
__device__ __forceinline__ void voxel_body(const float* __restrict__ vf,
                                           float4* sw, int blk) {
    int n = d_cnt[LVL];
    int base = blk * 64;
    if (base >= n) return;

    int tid = threadIdx.x;
    const float4* wsrc = (LVL == 0) ? (const float4*)d_G0
                        : (LVL == 1) ? (const float4*)d_G1
                                     : (const float4*)d_Wpt;
    for (int i = tid; i < 9 * C4; i += 256) sw[i] = wsrc[i];
    __syncthreads();

    int lane = tid & 31;
    int w    = tid >> 5;
    int sub  = lane >> 3;   // slot within warp (0..3)
    int cs   = lane & 7;    // channel lane (0..7)

    int idx0 = base + w * 8 + sub * 2;
    int idx1 = idx0 + 1;
    bool ok0 = idx0 < n;
    bool ok1 = idx1 < n;
    int2 e0 = ok0 ? d_list[LVL][idx0] : make_int2(0, 0);
    int2 e1 = ok1 ? d_list[LVL][idx1] : make_int2(0, 0);
    const float4* rowA = (const float4*)vf + (size_t)e0.y * C4;
    const float4* rowB = (const float4*)vf + (size_t)e1.y * C4;

    float accA[9], accB[9];
#pragma unroll
    for (int k = 0; k < 9; k++) { accA[k] = 0.f; accB[k] = 0.f; }

#pragma unroll 2
    for (int m = 0; m < C4 / 8; m++) {
        int c4 = cs + 8 * m;
        float4 va = rowA[c4];
        float4 vb = rowB[c4];
#pragma unroll
        for (int k = 0; k < 9; k++) {
            float4 wv = sw[k * C4 + c4];
            accA[k] += va.x * wv.x + va.y * wv.y + va.z * wv.z + va.w * wv.w;
            accB[k] += vb.x * wv.x + vb.y * wv.y + vb.z * wv.z + vb.w * wv.w;
        }
    }
#pragma unroll
    for (int k = 0; k < 9; k++) {
        float sA = accA[k];
        float sB = accB[k];
        sA += __shfl_xor_sync(0xffffffffu, sA, 1);
        sB += __shfl_xor_sync(0xffffffffu, sB, 1);
        sA += __shfl_xor_sync(0xffffffffu, sA, 2);
        sB += __shfl_xor_sync(0xffffffffu, sB, 2);
        sA += __shfl_xor_sync(0xffffffffu, sA, 4);
        sB += __shfl_xor_sync(0xffffffffu, sB, 4);
        if (cs == 0) {
            if (ok0) d_tv[LVL][k][e0.x] = sA;
            if (ok1) d_tv[LVL][k][e1.x] = sB;
        }
    }
}

// ---------------- K3: merged work kernel --------------------------------------
// blocks [0,1200): lvl2  [1200,2400): lvl1  [2400,3600): lvl0  [3600,3900): img
__global__ void __launch_bounds__(256, 4) k_work(const float* __restrict__ img,
                                                 const float* __restrict__ seg,
                                                 const float* __restrict__ vf0,
                                                 const float* __restrict__ vf1,
                                                 const float* __restrict__ vf2) {
    __shared__ __align__(16) float sw[3072];   // 12KB
    int b = blockIdx.x;
    if (b < 1200)      voxel_body<2, 64>(vf2, (float4*)sw, b);
    else if (b < 2400) voxel_body<1, 32>(vf1, (float4*)sw, b - 1200);
    else if (b < 3600) voxel_body<0, 16>(vf0, (float4*)sw, b - 2400);
    else               img_body(img, seg, sw, b - 3600);
}

// ---------------- K4: attention map (fuses tap-plane merge) -------------------
__global__ void k_att(const float* __restrict__ seg, const float* __restrict__ sbb) {
    int pix = blockIdx.x * 256 + threadIdx.x;
    int y = pix / Ww;
    int x = pix - y * Ww;
    float sum = sbb[0];
#pragma unroll
    for (int ky = 0; ky < 3; ky++) {
        int yy = y + ky - 1;
        if (yy < 0 || yy >= Hh) continue;
#pragma unroll
        for (int kx = 0; kx < 3; kx++) {
            int xx = x + kx - 1;
            if (xx < 0 || xx >= Ww) continue;
            int kk = ky * 3 + kx;
            int ni = yy * Ww + xx;
            sum += d_ti[kk][ni] + d_tv[0][kk][ni] + d_tv[1][kk][ni] + d_tv[2][kk][ni];
        }
    }
    float att = 1.f / (1.f + expf(-sum));
    d_att[pix] = att * seg[HW + pix];
}

// ---------------- K5: out = img * gated attention, pure stream ----------------
// grid = 256 channels * 75 blocks; block handles 256 float4 of one channel
__global__ void k_out(const float4* __restrict__ img, float4* __restrict__ out) {
    int c = blockIdx.x / 75;
    int i4 = (blockIdx.x % 75) * 256 + threadIdx.x;      // float4 idx within channel
    float4 a = ((const float4*)d_att)[i4];
    size_t g = (size_t)c * (HW / 4) + i4;
    float4 v = img[g];
    v.x *= a.x; v.y *= a.y; v.z *= a.z; v.w *= a.w;
    out[g] = v;
}

extern "C" void kernel_launch(void* const* d_in, const int* in_sizes, int n_in,
                              void* d_out, int out_size) {
    const float* img = (const float*)d_in[0];
    const float* seg = (const float*)d_in[1];

    int iv0, iv1, iv2, ig0, ig1, ig2;
    if (in_sizes[3] == 2 * NP) { iv0 = 2; ig0 = 3; iv1 = 4; ig1 = 5; iv2 = 6; ig2 = 7; }
    else                       { iv0 = 2; iv1 = 3; iv2 = 4; ig0 = 5; ig1 = 6; ig2 = 7; }

    const float* vf0 = (const float*)d_in[iv0];
    const float* vf1 = (const float*)d_in[iv1];
    const float* vf2 = (const float*)d_in[iv2];
    const int*   g0  = (const int*)d_in[ig0];
    const int*   g1  = (const int*)d_in[ig1];
    const int*   g2  = (const int*)d_in[ig2];
    const float* rw0 = (const float*)d_in[8];
    const float* rb0 = (const float*)d_in[9];
    const float* rw1 = (const float*)d_in[10];
    const float* rb1 = (const float*)d_in[11];
    const float* sbw = (const float*)d_in[12];
    const float* sbb = (const float*)d_in[13];

    k_initprep<<<2034, 256>>>(rw0, rb0, rw1, rb1, sbw);
    k_scatter<<<(3 * NP + 255) / 256, 256>>>(g0, g1, g2);
    k_compact<<<900, 256>>>();
    k_work<<<3900, 256>>>(img, seg, vf0, vf1, vf2);
    k_att<<<HW / 256, 256>>>(seg, sbb);
    k_out<<<256 * 75, 256>>>((const float4*)img, (float4*)d_out);
}